// round 11
// baseline (speedup 1.0000x reference)
#include <cuda_runtime.h>
#include <cuda_bf16.h>
#include <math.h>
#include <stdint.h>

// Problem constants
#define BB 16
#define CC 256
#define CI 128
#define HH 64
#define WW2 64
#define NN 4096    // H*W
#define MM 1024    // (H/2)*(W/2)

#define LOG2E 1.4426950408889634f

// ---------------------------------------------------------------------------
// Scratch (device globals -- allocation-free rule)
// ---------------------------------------------------------------------------
__device__ __nv_bfloat16 g_QH[BB * NN * CI];   // [b][n][c]  Q bf16 (pre-scaled by log2e)
__device__ __nv_bfloat16 g_KH[BB * MM * CI];   // [b][m][c]  K bf16 (pooled phi)
__device__ __nv_bfloat16 g_VH[BB * CI * MM];   // [b][c][m]  V bf16 (pooled g)
__device__ __nv_bfloat16 g_WH[CC * CI];        // [o][c]     W_w bf16

// ---------------------------------------------------------------------------
// PTX helpers
// ---------------------------------------------------------------------------
__device__ __forceinline__ uint32_t f2tf32(float x) {
    uint32_t r;
    asm("cvt.rna.tf32.f32 %0, %1;" : "=r"(r) : "f"(x));
    return r;
}
__device__ __forceinline__ float tf32r(float x) { return __uint_as_float(f2tf32(x)); }

__device__ __forceinline__ float ex2f(float x) {
    float r;
    asm("ex2.approx.f32 %0, %1;" : "=f"(r) : "f"(x));
    return r;
}

__device__ __forceinline__ void mma_tf32(float c[4],
                                         uint32_t a0, uint32_t a1, uint32_t a2, uint32_t a3,
                                         uint32_t b0, uint32_t b1) {
    asm volatile(
        "mma.sync.aligned.m16n8k8.row.col.f32.tf32.tf32.f32 "
        "{%0,%1,%2,%3}, {%4,%5,%6,%7}, {%8,%9}, {%0,%1,%2,%3};\n"
        : "+f"(c[0]), "+f"(c[1]), "+f"(c[2]), "+f"(c[3])
        : "r"(a0), "r"(a1), "r"(a2), "r"(a3), "r"(b0), "r"(b1));
}

__device__ __forceinline__ void mma_bf16(float c[4],
                                         uint32_t a0, uint32_t a1, uint32_t a2, uint32_t a3,
                                         uint32_t b0, uint32_t b1) {
    asm volatile(
        "mma.sync.aligned.m16n8k16.row.col.f32.bf16.bf16.f32 "
        "{%0,%1,%2,%3}, {%4,%5,%6,%7}, {%8,%9}, {%0,%1,%2,%3};\n"
        : "+f"(c[0]), "+f"(c[1]), "+f"(c[2]), "+f"(c[3])
        : "r"(a0), "r"(a1), "r"(a2), "r"(a3), "r"(b0), "r"(b1));
}

__device__ __forceinline__ uint32_t pack_bf16(float lo, float hi) {
    uint32_t r;
    asm("cvt.rn.bf16x2.f32 %0, %1, %2;" : "=r"(r) : "f"(hi), "f"(lo));
    return r;
}

__device__ __forceinline__ void cp_async16(void* smem_dst, const void* gsrc) {
    uint32_t s = (uint32_t)__cvta_generic_to_shared(smem_dst);
    asm volatile("cp.async.cg.shared.global [%0], [%1], 16;\n" :: "r"(s), "l"(gsrc));
}
#define CP_COMMIT() asm volatile("cp.async.commit_group;\n" ::: "memory")
#define CP_WAIT0()  asm volatile("cp.async.wait_group 0;\n" ::: "memory")

// ---------------------------------------------------------------------------
// Kernel A: theta/phi/g GEMM (tf32 MMA), block 128o x 128n, warp tile 32x64.
// blockIdx.y: 0 = theta (-> Q transposed, scaled by log2e),
//             1 = phi (-> pool+transpose -> K), 2 = g (-> pool -> V).
// ---------------------------------------------------------------------------
#define PAS 36                       // As stride: bank = 4g+tig, conflict-free
#define PXS 136                      // Xs stride: bank = 8tig+g, conflict-free
#define PROJ_BUF (128 * PAS + 32 * PXS)     // 8960 floats
#define PROJ_SMEM_BYTES (2 * PROJ_BUF * 4)  // 71680
#define TTS 130                      // epilogue tile stride (bf16)

__global__ __launch_bounds__(256, 2) void proj_kernel(
    const float* __restrict__ x,
    const float* __restrict__ theta_w, const float* __restrict__ theta_b,
    const float* __restrict__ phi_w,   const float* __restrict__ phi_b,
    const float* __restrict__ gw,      const float* __restrict__ gb)
{
    extern __shared__ float psm[];

    const int b  = blockIdx.z;
    const int ot = blockIdx.y;            // 0 theta, 1 phi, 2 g
    const int n0 = blockIdx.x * 128;
    const int tid  = threadIdx.x;
    const int warp = tid >> 5, lane = tid & 31;
    const int g = lane >> 2, tig = lane & 3;
    const int wo = warp >> 1;             // 0..3
    const int wn = warp & 1;              // 0..1
    const int obase = wo * 32, nbase = wn * 64;

    const float* wsel; const float* bsel;
    if (ot == 0)      { wsel = theta_w; bsel = theta_b; }
    else if (ot == 1) { wsel = phi_w;   bsel = phi_b;   }
    else              { wsel = gw;      bsel = gb;      }

    float  wreg[16];
    float4 xreg[4];

    auto ldchunk = [&](int k0) {
        #pragma unroll
        for (int i = 0; i < 16; i++) {
            int e = tid + i * 256;
            int o = e >> 5, kc = e & 31;
            wreg[i] = wsel[o * CC + k0 + kc];
        }
        #pragma unroll
        for (int i = 0; i < 4; i++) {
            int e = tid + i * 256;
            int kc = e >> 5, n4 = e & 31;
            xreg[i] = *(const float4*)&x[(b * CC + k0 + kc) * NN + n0 + n4 * 4];
        }
    };
    auto stchunk = [&](float* buf) {
        #pragma unroll
        for (int i = 0; i < 16; i++) {
            int e = tid + i * 256;
            int o = e >> 5, kc = e & 31;
            buf[o * PAS + kc] = tf32r(wreg[i]);
        }
        float* Xs = buf + 128 * PAS;
        #pragma unroll
        for (int i = 0; i < 4; i++) {
            int e = tid + i * 256;
            int kc = e >> 5, n4 = e & 31;
            float4 v = xreg[i];
            v.x = tf32r(v.x); v.y = tf32r(v.y); v.z = tf32r(v.z); v.w = tf32r(v.w);
            *(float4*)&Xs[kc * PXS + n4 * 4] = v;
        }
    };

    float acc[2][8][4] = {};

    ldchunk(0);
    stchunk(psm);
    ldchunk(32);

    for (int kc_i = 0; kc_i < 8; kc_i++) {
        __syncthreads();
        const float* As = psm + (kc_i & 1) * PROJ_BUF;
        const float* Xs = As + 128 * PAS;
        if (kc_i < 7) stchunk(psm + ((kc_i + 1) & 1) * PROJ_BUF);
        if (kc_i < 6) ldchunk((kc_i + 2) * 32);

        #pragma unroll
        for (int s = 0; s < 4; s++) {
            uint32_t a[2][4];
            #pragma unroll
            for (int mi = 0; mi < 2; mi++) {
                const int orow = obase + mi * 16;
                a[mi][0] = __float_as_uint(As[(orow + g)     * PAS + s * 8 + tig]);
                a[mi][1] = __float_as_uint(As[(orow + g + 8) * PAS + s * 8 + tig]);
                a[mi][2] = __float_as_uint(As[(orow + g)     * PAS + s * 8 + tig + 4]);
                a[mi][3] = __float_as_uint(As[(orow + g + 8) * PAS + s * 8 + tig + 4]);
            }
            #pragma unroll
            for (int nt = 0; nt < 8; nt++) {
                uint32_t b0 = __float_as_uint(Xs[(s * 8 + tig)     * PXS + nbase + nt * 8 + g]);
                uint32_t b1 = __float_as_uint(Xs[(s * 8 + tig + 4) * PXS + nbase + nt * 8 + g]);
                mma_tf32(acc[0][nt], a[0][0], a[0][1], a[0][2], a[0][3], b0, b1);
                mma_tf32(acc[1][nt], a[1][0], a[1][1], a[1][2], a[1][3], b0, b1);
            }
        }
    }

    // ---- epilogue: acc -> bf16 tile T[128 o][TTS], then route ----
    __syncthreads();
    __nv_bfloat16* T = (__nv_bfloat16*)psm;
    const float mult = (ot == 0) ? LOG2E : 1.0f;   // fold log2e into Q

    #pragma unroll
    for (int mi = 0; mi < 2; mi++) {
        #pragma unroll
        for (int half = 0; half < 2; half++) {
            const int olocal = obase + mi * 16 + g + half * 8;
            const float bias = bsel[olocal];
            #pragma unroll
            for (int nt = 0; nt < 8; nt++) {
                const int n = nbase + nt * 8 + tig * 2;
                __nv_bfloat162 pr = __float22bfloat162_rn(
                    make_float2((acc[mi][nt][half * 2 + 0] + bias) * mult,
                                (acc[mi][nt][half * 2 + 1] + bias) * mult));
                *(__nv_bfloat162*)&T[olocal * TTS + n] = pr;
            }
        }
    }
    __syncthreads();

    if (ot == 0) {
        // theta: transpose -> g_QH[b][n0+n][c]
        #pragma unroll
        for (int i2 = 0; i2 < 32; i2++) {
            int e = tid + i2 * 256;
            int u = e & 63, n = e >> 6;
            __nv_bfloat162 v;
            v.x = T[(2 * u)     * TTS + n];
            v.y = T[(2 * u + 1) * TTS + n];
            *(__nv_bfloat162*)&g_QH[((size_t)b * NN + n0 + n) * CI + 2 * u] = v;
        }
    } else if (ot == 1) {
        // phi: 2x2 pool + transpose -> g_KH[b][m0+j][c]
        const int m0 = blockIdx.x * 32;
        #pragma unroll
        for (int i2 = 0; i2 < 8; i2++) {
            int e = tid + i2 * 256;
            int u = e & 63, j = e >> 6;
            const __nv_bfloat16* r0 = T + (2 * u) * TTS;
            const __nv_bfloat16* r1 = T + (2 * u + 1) * TTS;
            float a0 = fmaxf(fmaxf(__bfloat162float(r0[2 * j]),
                                   __bfloat162float(r0[2 * j + 1])),
                             fmaxf(__bfloat162float(r0[64 + 2 * j]),
                                   __bfloat162float(r0[64 + 2 * j + 1])));
            float a1 = fmaxf(fmaxf(__bfloat162float(r1[2 * j]),
                                   __bfloat162float(r1[2 * j + 1])),
                             fmaxf(__bfloat162float(r1[64 + 2 * j]),
                                   __bfloat162float(r1[64 + 2 * j + 1])));
            __nv_bfloat162 v;
            v.x = __float2bfloat16(a0);
            v.y = __float2bfloat16(a1);
            *(__nv_bfloat162*)&g_KH[((size_t)b * MM + m0 + j) * CI + 2 * u] = v;
        }
    } else {
        // g: 2x2 pool -> g_VH[b][c][m0+j]
        const int m0 = blockIdx.x * 32;
        #pragma unroll
        for (int i2 = 0; i2 < 16; i2++) {
            int e = tid + i2 * 256;
            int c = e >> 5, j = e & 31;
            const __nv_bfloat16* r = T + c * TTS;
            float v = fmaxf(fmaxf(__bfloat162float(r[2 * j]),
                                  __bfloat162float(r[2 * j + 1])),
                            fmaxf(__bfloat162float(r[64 + 2 * j]),
                                  __bfloat162float(r[64 + 2 * j + 1])));
            g_VH[((size_t)b * CI + c) * MM + m0 + j] = __float2bfloat16(v);
        }
    }
}

// ---------------------------------------------------------------------------
// Kernel B: W_w fp32 [o][c] -> bf16 g_WH [o][c]
// ---------------------------------------------------------------------------
__global__ __launch_bounds__(256) void wprep_kernel(const float* __restrict__ W_w)
{
    const int idx = blockIdx.x * 256 + threadIdx.x;
    g_WH[idx] = __float2bfloat16(W_w[idx]);
}

// ---------------------------------------------------------------------------
// Kernel C: bf16 flash attention (fixed-max softmax via ex2, Q pre-scaled)
// + fused final conv/BN/residual. Chunks of 64 keys, double-buffered.
// Q resident in smem (fragments reloaded per chunk). 2 blocks/SM.
// ---------------------------------------------------------------------------
#define KROWB 272                  // 256B + 16 pad
#define VROWB 144                  // 128B + 16 pad
#define QBYTES (128 * KROWB)       // 34816
#define KBYTES (64 * KROWB)        // 17408
#define VBYTES (128 * VROWB)       // 18432
#define OFF_Q  0
#define OFF_K0 QBYTES
#define OFF_K1 (QBYTES + KBYTES)
#define OFF_V0 (QBYTES + 2 * KBYTES)
#define OFF_V1 (QBYTES + 2 * KBYTES + VBYTES)
#define ATTN_SMEM_BYTES (QBYTES + 2 * KBYTES + 2 * VBYTES)   // 106496

__global__ __launch_bounds__(256, 2) void attn_kernel(
    const float* __restrict__ x,
    const float* __restrict__ W_b,
    const float* __restrict__ bn_gamma, const float* __restrict__ bn_beta,
    const float* __restrict__ bn_mean,  const float* __restrict__ bn_var,
    float* __restrict__ out)
{
    extern __shared__ char smc[];

    const int b  = blockIdx.y;
    const int q0 = blockIdx.x * 128;
    const int tid  = threadIdx.x;
    const int warp = tid >> 5, lane = tid & 31;
    const int g = lane >> 2, tig = lane & 3;
    const int qbase = warp * 16;

    // ---- prologue: Q, K0, V0 ----
    #pragma unroll
    for (int i = 0; i < 8; i++) {
        int gi = tid + i * 256;
        int n = gi >> 4, c16 = gi & 15;
        cp_async16(smc + OFF_Q + n * KROWB + c16 * 16,
                   (const char*)&g_QH[((size_t)b * NN + q0 + n) * CI] + c16 * 16);
    }
    #pragma unroll
    for (int i = 0; i < 4; i++) {
        int gi = tid + i * 256;
        int key = gi >> 4, c16 = gi & 15;
        cp_async16(smc + OFF_K0 + key * KROWB + c16 * 16,
                   (const char*)&g_KH[((size_t)b * MM + key) * CI] + c16 * 16);
    }
    #pragma unroll
    for (int i = 0; i < 4; i++) {
        int gi = tid + i * 256;
        int ch = gi >> 3, k16 = gi & 7;
        cp_async16(smc + OFF_V0 + ch * VROWB + k16 * 16,
                   (const char*)&g_VH[((size_t)b * CI + ch) * MM] + k16 * 16);
    }
    CP_COMMIT();

    const char* qwb = smc + OFF_Q + (qbase + g) * KROWB + tig * 4;

    float l_lo = 0.0f, l_hi = 0.0f;
    float yacc[16][4] = {};

    for (int mt = 0; mt < MM / 64; mt++) {
        CP_WAIT0();
        __syncthreads();

        if (mt + 1 < MM / 64) {
            const int m0n = (mt + 1) * 64;
            const int kb = ((mt + 1) & 1) ? OFF_K1 : OFF_K0;
            const int vb = ((mt + 1) & 1) ? OFF_V1 : OFF_V0;
            #pragma unroll
            for (int i = 0; i < 4; i++) {
                int gi = tid + i * 256;
                int key = gi >> 4, c16 = gi & 15;
                cp_async16(smc + kb + key * KROWB + c16 * 16,
                           (const char*)&g_KH[((size_t)b * MM + m0n + key) * CI] + c16 * 16);
            }
            #pragma unroll
            for (int i = 0; i < 4; i++) {
                int gi = tid + i * 256;
                int ch = gi >> 3, k16 = gi & 7;
                cp_async16(smc + vb + ch * VROWB + k16 * 16,
                           (const char*)&g_VH[((size_t)b * CI + ch) * MM + m0n] + k16 * 16);
            }
            CP_COMMIT();
        }

        const char* Kb = smc + ((mt & 1) ? OFF_K1 : OFF_K0);
        const char* Vb = smc + ((mt & 1) ? OFF_V1 : OFF_V0);
        const char* kwb = Kb + g * KROWB + tig * 4;
        const char* vwb = Vb + g * VROWB + tig * 4;

        // ---- S = Q K^T (64 keys); Q frags reloaded from smem ----
        float sacc[8][4] = {};
        #pragma unroll
        for (int s = 0; s < 8; s++) {
            uint32_t a0 = *(const uint32_t*)(qwb + s * 32);
            uint32_t a1 = *(const uint32_t*)(qwb + 8 * KROWB + s * 32);
            uint32_t a2 = *(const uint32_t*)(qwb + s * 32 + 16);
            uint32_t a3 = *(const uint32_t*)(qwb + 8 * KROWB + s * 32 + 16);
            #pragma unroll
            for (int nt = 0; nt < 8; nt++) {
                uint32_t b0 = *(const uint32_t*)(kwb + nt * (8 * KROWB) + s * 32);
                uint32_t b1 = *(const uint32_t*)(kwb + nt * (8 * KROWB) + s * 32 + 16);
                mma_bf16(sacc[nt], a0, a1, a2, a3, b0, b1);
            }
        }

        // ---- fixed-max softmax: p = 2^(min(s', 115)) (s' = s*log2e) ----
        #pragma unroll
        for (int nt = 0; nt < 8; nt++) {
            sacc[nt][0] = ex2f(fminf(sacc[nt][0], 115.0f));
            sacc[nt][1] = ex2f(fminf(sacc[nt][1], 115.0f));
            sacc[nt][2] = ex2f(fminf(sacc[nt][2], 115.0f));
            sacc[nt][3] = ex2f(fminf(sacc[nt][3], 115.0f));
            l_lo += sacc[nt][0] + sacc[nt][1];
            l_hi += sacc[nt][2] + sacc[nt][3];
        }

        // ---- Y += P V^T ----
        #pragma unroll
        for (int s2 = 0; s2 < 4; s2++) {
            uint32_t a0 = pack_bf16(sacc[2*s2][0],   sacc[2*s2][1]);
            uint32_t a1 = pack_bf16(sacc[2*s2][2],   sacc[2*s2][3]);
            uint32_t a2 = pack_bf16(sacc[2*s2+1][0], sacc[2*s2+1][1]);
            uint32_t a3 = pack_bf16(sacc[2*s2+1][2], sacc[2*s2+1][3]);
            #pragma unroll
            for (int nt = 0; nt < 16; nt++) {
                uint32_t b0 = *(const uint32_t*)(vwb + nt * (8 * VROWB) + s2 * 32);
                uint32_t b1 = *(const uint32_t*)(vwb + nt * (8 * VROWB) + s2 * 32 + 16);
                mma_bf16(yacc[nt], a0, a1, a2, a3, b0, b1);
            }
        }
    }

    // ---- normalize y, pack bf16 into Ys (aliases Q buffer; warp-local rows) ----
    l_lo += __shfl_xor_sync(0xffffffffu, l_lo, 1);
    l_lo += __shfl_xor_sync(0xffffffffu, l_lo, 2);
    l_hi += __shfl_xor_sync(0xffffffffu, l_hi, 1);
    l_hi += __shfl_xor_sync(0xffffffffu, l_hi, 2);
    const float inv_lo = 1.0f / l_lo;
    const float inv_hi = 1.0f / l_hi;

    char* Ysb = smc + OFF_Q;      // rows = local query n, cols = c (bf16)
    #pragma unroll
    for (int nt = 0; nt < 16; nt++) {
        const int c = nt * 8 + tig * 2;
        *(uint32_t*)(Ysb + (qbase + g)     * KROWB + c * 2) =
            pack_bf16(yacc[nt][0] * inv_lo, yacc[nt][1] * inv_lo);
        *(uint32_t*)(Ysb + (qbase + g + 8) * KROWB + c * 2) =
            pack_bf16(yacc[nt][2] * inv_hi, yacc[nt][3] * inv_hi);
    }
    __syncthreads();

    // ---- fused final conv: out[o][n] = BN(W@y + W_b) + x, 2 o-passes ----
    const char* ywb = Ysb + g * KROWB + tig * 4;
    const uint32_t* Wg = (const uint32_t*)g_WH;   // bf16 pairs

    #pragma unroll
    for (int p = 0; p < 2; p++) {
        const int obase2 = p * 128 + warp * 16;
        float facc[16][4] = {};
        #pragma unroll
        for (int s = 0; s < 8; s++) {
            // W A-fragment via direct LDG (L2-resident, 64 KB total)
            uint32_t a0 = Wg[(obase2 + g)     * 64 + s * 8 + tig];
            uint32_t a1 = Wg[(obase2 + g + 8) * 64 + s * 8 + tig];
            uint32_t a2 = Wg[(obase2 + g)     * 64 + s * 8 + tig + 4];
            uint32_t a3 = Wg[(obase2 + g + 8) * 64 + s * 8 + tig + 4];
            #pragma unroll
            for (int nt = 0; nt < 16; nt++) {
                uint32_t b0 = *(const uint32_t*)(ywb + nt * (8 * KROWB) + s * 32);
                uint32_t b1 = *(const uint32_t*)(ywb + nt * (8 * KROWB) + s * 32 + 16);
                mma_bf16(facc[nt], a0, a1, a2, a3, b0, b1);
            }
        }
        // BN + bias + residual
        #pragma unroll
        for (int half = 0; half < 2; half++) {
            const int o = obase2 + g + half * 8;
            const float scale = bn_gamma[o] * rsqrtf(bn_var[o] + 1e-5f);
            const float shift = bn_beta[o] - bn_mean[o] * scale + W_b[o] * scale;
            const size_t base = ((size_t)b * CC + o) * NN + q0;
            #pragma unroll
            for (int nt = 0; nt < 16; nt++) {
                const int n = nt * 8 + tig * 2;
                float2 xr = *(const float2*)&x[base + n];
                float2 v;
                v.x = facc[nt][half * 2 + 0] * scale + shift + xr.x;
                v.y = facc[nt][half * 2 + 1] * scale + shift + xr.y;
                *(float2*)&out[base + n] = v;
            }
        }
    }
}

// ---------------------------------------------------------------------------
// Launch
// ---------------------------------------------------------------------------
extern "C" void kernel_launch(void* const* d_in, const int* in_sizes, int n_in,
                              void* d_out, int out_size)
{
    (void)in_sizes; (void)n_in; (void)out_size;

    const float* x        = (const float*)d_in[0];
    const float* theta_w  = (const float*)d_in[1];
    const float* theta_b  = (const float*)d_in[2];
    const float* phi_w    = (const float*)d_in[3];
    const float* phi_b    = (const float*)d_in[4];
    const float* gw       = (const float*)d_in[5];
    const float* gb       = (const float*)d_in[6];
    const float* W_w      = (const float*)d_in[7];
    const float* W_b      = (const float*)d_in[8];
    const float* bn_gamma = (const float*)d_in[9];
    const float* bn_beta  = (const float*)d_in[10];
    const float* bn_mean  = (const float*)d_in[11];
    const float* bn_var   = (const float*)d_in[12];
    float* out = (float*)d_out;

    cudaFuncSetAttribute(proj_kernel,
                         cudaFuncAttributeMaxDynamicSharedMemorySize, PROJ_SMEM_BYTES);
    cudaFuncSetAttribute(attn_kernel,
                         cudaFuncAttributeMaxDynamicSharedMemorySize, ATTN_SMEM_BYTES);

    // A: projections with fused pool/transpose epilogues
    {
        dim3 grid(32, 3, BB);
        proj_kernel<<<grid, 256, PROJ_SMEM_BYTES>>>(x, theta_w, theta_b,
                                                    phi_w, phi_b, gw, gb);
    }
    // B: W -> bf16
    wprep_kernel<<<(CC * CI) / 256, 256>>>(W_w);
    // C: flash attention + fused final conv/BN/residual
    {
        dim3 grid(NN / 128, BB);
        attn_kernel<<<grid, 256, ATTN_SMEM_BYTES>>>(x, W_b, bn_gamma, bn_beta,
                                                    bn_mean, bn_var, out);
    }
}

// round 12
// speedup vs baseline: 1.1718x; 1.1718x over previous
#include <cuda_runtime.h>
#include <cuda_bf16.h>
#include <math.h>
#include <stdint.h>

// Problem constants
#define BB 16
#define CC 256
#define CI 128
#define HH 64
#define WW2 64
#define NN 4096    // H*W
#define MM 1024    // (H/2)*(W/2)

#define LOG2E 1.4426950408889634f

// ---------------------------------------------------------------------------
// Scratch (device globals -- allocation-free rule)
// ---------------------------------------------------------------------------
__device__ __nv_bfloat16 g_QH[BB * NN * CI];   // [b][n][c]  Q bf16 (pre-scaled by log2e)
__device__ __nv_bfloat16 g_KH[BB * MM * CI];   // [b][m][c]  K bf16 (pooled phi)
__device__ __nv_bfloat16 g_VH[BB * CI * MM];   // [b][c][m]  V bf16 (pooled g)
__device__ __nv_bfloat16 g_WH[CC * CI];        // [o][c]     W_w bf16

// ---------------------------------------------------------------------------
// PTX helpers
// ---------------------------------------------------------------------------
__device__ __forceinline__ uint32_t f2tf32(float x) {
    uint32_t r;
    asm("cvt.rna.tf32.f32 %0, %1;" : "=r"(r) : "f"(x));
    return r;
}
__device__ __forceinline__ float tf32r(float x) { return __uint_as_float(f2tf32(x)); }

__device__ __forceinline__ float ex2f(float x) {
    float r;
    asm("ex2.approx.f32 %0, %1;" : "=f"(r) : "f"(x));
    return r;
}

__device__ __forceinline__ void mma_tf32(float c[4],
                                         uint32_t a0, uint32_t a1, uint32_t a2, uint32_t a3,
                                         uint32_t b0, uint32_t b1) {
    asm volatile(
        "mma.sync.aligned.m16n8k8.row.col.f32.tf32.tf32.f32 "
        "{%0,%1,%2,%3}, {%4,%5,%6,%7}, {%8,%9}, {%0,%1,%2,%3};\n"
        : "+f"(c[0]), "+f"(c[1]), "+f"(c[2]), "+f"(c[3])
        : "r"(a0), "r"(a1), "r"(a2), "r"(a3), "r"(b0), "r"(b1));
}

__device__ __forceinline__ void mma_bf16(float c[4],
                                         uint32_t a0, uint32_t a1, uint32_t a2, uint32_t a3,
                                         uint32_t b0, uint32_t b1) {
    asm volatile(
        "mma.sync.aligned.m16n8k16.row.col.f32.bf16.bf16.f32 "
        "{%0,%1,%2,%3}, {%4,%5,%6,%7}, {%8,%9}, {%0,%1,%2,%3};\n"
        : "+f"(c[0]), "+f"(c[1]), "+f"(c[2]), "+f"(c[3])
        : "r"(a0), "r"(a1), "r"(a2), "r"(a3), "r"(b0), "r"(b1));
}

__device__ __forceinline__ uint32_t pack_bf16(float lo, float hi) {
    uint32_t r;
    asm("cvt.rn.bf16x2.f32 %0, %1, %2;" : "=r"(r) : "f"(hi), "f"(lo));
    return r;
}

__device__ __forceinline__ void cp_async16(void* smem_dst, const void* gsrc) {
    uint32_t s = (uint32_t)__cvta_generic_to_shared(smem_dst);
    asm volatile("cp.async.cg.shared.global [%0], [%1], 16;\n" :: "r"(s), "l"(gsrc));
}
#define CP_COMMIT() asm volatile("cp.async.commit_group;\n" ::: "memory")
#define CP_WAIT0()  asm volatile("cp.async.wait_group 0;\n" ::: "memory")
#define CP_WAIT1()  asm volatile("cp.async.wait_group 1;\n" ::: "memory")

// ---------------------------------------------------------------------------
// Kernel A (R11, verified -25us): theta/phi/g GEMM (tf32 MMA),
// block 128o x 128n, warp tile 32x64, conflict-free strides.
// blockIdx.y: 0 = theta (-> Q transposed, scaled by log2e),
//             1 = phi (-> pool+transpose -> K), 2 = g (-> pool -> V).
// ---------------------------------------------------------------------------
#define PAS 36                       // As stride: bank = 4g+tig
#define PXS 136                      // Xs stride: bank = 8tig+g
#define PROJ_BUF (128 * PAS + 32 * PXS)     // 8960 floats
#define PROJ_SMEM_BYTES (2 * PROJ_BUF * 4)  // 71680
#define TTS 130                      // epilogue tile stride (bf16)

__global__ __launch_bounds__(256, 2) void proj_kernel(
    const float* __restrict__ x,
    const float* __restrict__ theta_w, const float* __restrict__ theta_b,
    const float* __restrict__ phi_w,   const float* __restrict__ phi_b,
    const float* __restrict__ gw,      const float* __restrict__ gb)
{
    extern __shared__ float psm[];

    const int b  = blockIdx.z;
    const int ot = blockIdx.y;            // 0 theta, 1 phi, 2 g
    const int n0 = blockIdx.x * 128;
    const int tid  = threadIdx.x;
    const int warp = tid >> 5, lane = tid & 31;
    const int g = lane >> 2, tig = lane & 3;
    const int wo = warp >> 1;             // 0..3
    const int wn = warp & 1;              // 0..1
    const int obase = wo * 32, nbase = wn * 64;

    const float* wsel; const float* bsel;
    if (ot == 0)      { wsel = theta_w; bsel = theta_b; }
    else if (ot == 1) { wsel = phi_w;   bsel = phi_b;   }
    else              { wsel = gw;      bsel = gb;      }

    float  wreg[16];
    float4 xreg[4];

    auto ldchunk = [&](int k0) {
        #pragma unroll
        for (int i = 0; i < 16; i++) {
            int e = tid + i * 256;
            int o = e >> 5, kc = e & 31;
            wreg[i] = wsel[o * CC + k0 + kc];
        }
        #pragma unroll
        for (int i = 0; i < 4; i++) {
            int e = tid + i * 256;
            int kc = e >> 5, n4 = e & 31;
            xreg[i] = *(const float4*)&x[(b * CC + k0 + kc) * NN + n0 + n4 * 4];
        }
    };
    auto stchunk = [&](float* buf) {
        #pragma unroll
        for (int i = 0; i < 16; i++) {
            int e = tid + i * 256;
            int o = e >> 5, kc = e & 31;
            buf[o * PAS + kc] = tf32r(wreg[i]);
        }
        float* Xs = buf + 128 * PAS;
        #pragma unroll
        for (int i = 0; i < 4; i++) {
            int e = tid + i * 256;
            int kc = e >> 5, n4 = e & 31;
            float4 v = xreg[i];
            v.x = tf32r(v.x); v.y = tf32r(v.y); v.z = tf32r(v.z); v.w = tf32r(v.w);
            *(float4*)&Xs[kc * PXS + n4 * 4] = v;
        }
    };

    float acc[2][8][4] = {};

    ldchunk(0);
    stchunk(psm);
    ldchunk(32);

    for (int kc_i = 0; kc_i < 8; kc_i++) {
        __syncthreads();
        const float* As = psm + (kc_i & 1) * PROJ_BUF;
        const float* Xs = As + 128 * PAS;
        if (kc_i < 7) stchunk(psm + ((kc_i + 1) & 1) * PROJ_BUF);
        if (kc_i < 6) ldchunk((kc_i + 2) * 32);

        #pragma unroll
        for (int s = 0; s < 4; s++) {
            uint32_t a[2][4];
            #pragma unroll
            for (int mi = 0; mi < 2; mi++) {
                const int orow = obase + mi * 16;
                a[mi][0] = __float_as_uint(As[(orow + g)     * PAS + s * 8 + tig]);
                a[mi][1] = __float_as_uint(As[(orow + g + 8) * PAS + s * 8 + tig]);
                a[mi][2] = __float_as_uint(As[(orow + g)     * PAS + s * 8 + tig + 4]);
                a[mi][3] = __float_as_uint(As[(orow + g + 8) * PAS + s * 8 + tig + 4]);
            }
            #pragma unroll
            for (int nt = 0; nt < 8; nt++) {
                uint32_t b0 = __float_as_uint(Xs[(s * 8 + tig)     * PXS + nbase + nt * 8 + g]);
                uint32_t b1 = __float_as_uint(Xs[(s * 8 + tig + 4) * PXS + nbase + nt * 8 + g]);
                mma_tf32(acc[0][nt], a[0][0], a[0][1], a[0][2], a[0][3], b0, b1);
                mma_tf32(acc[1][nt], a[1][0], a[1][1], a[1][2], a[1][3], b0, b1);
            }
        }
    }

    // ---- epilogue: acc -> bf16 tile T[128 o][TTS], then route ----
    __syncthreads();
    __nv_bfloat16* T = (__nv_bfloat16*)psm;
    const float mult = (ot == 0) ? LOG2E : 1.0f;   // fold log2e into Q

    #pragma unroll
    for (int mi = 0; mi < 2; mi++) {
        #pragma unroll
        for (int half = 0; half < 2; half++) {
            const int olocal = obase + mi * 16 + g + half * 8;
            const float bias = bsel[olocal];
            #pragma unroll
            for (int nt = 0; nt < 8; nt++) {
                const int n = nbase + nt * 8 + tig * 2;
                __nv_bfloat162 pr = __float22bfloat162_rn(
                    make_float2((acc[mi][nt][half * 2 + 0] + bias) * mult,
                                (acc[mi][nt][half * 2 + 1] + bias) * mult));
                *(__nv_bfloat162*)&T[olocal * TTS + n] = pr;
            }
        }
    }
    __syncthreads();

    if (ot == 0) {
        // theta: transpose -> g_QH[b][n0+n][c]
        #pragma unroll
        for (int i2 = 0; i2 < 32; i2++) {
            int e = tid + i2 * 256;
            int u = e & 63, n = e >> 6;
            __nv_bfloat162 v;
            v.x = T[(2 * u)     * TTS + n];
            v.y = T[(2 * u + 1) * TTS + n];
            *(__nv_bfloat162*)&g_QH[((size_t)b * NN + n0 + n) * CI + 2 * u] = v;
        }
    } else if (ot == 1) {
        // phi: 2x2 pool + transpose -> g_KH[b][m0+j][c]
        const int m0 = blockIdx.x * 32;
        #pragma unroll
        for (int i2 = 0; i2 < 8; i2++) {
            int e = tid + i2 * 256;
            int u = e & 63, j = e >> 6;
            const __nv_bfloat16* r0 = T + (2 * u) * TTS;
            const __nv_bfloat16* r1 = T + (2 * u + 1) * TTS;
            float a0 = fmaxf(fmaxf(__bfloat162float(r0[2 * j]),
                                   __bfloat162float(r0[2 * j + 1])),
                             fmaxf(__bfloat162float(r0[64 + 2 * j]),
                                   __bfloat162float(r0[64 + 2 * j + 1])));
            float a1 = fmaxf(fmaxf(__bfloat162float(r1[2 * j]),
                                   __bfloat162float(r1[2 * j + 1])),
                             fmaxf(__bfloat162float(r1[64 + 2 * j]),
                                   __bfloat162float(r1[64 + 2 * j + 1])));
            __nv_bfloat162 v;
            v.x = __float2bfloat16(a0);
            v.y = __float2bfloat16(a1);
            *(__nv_bfloat162*)&g_KH[((size_t)b * MM + m0 + j) * CI + 2 * u] = v;
        }
    } else {
        // g: 2x2 pool -> g_VH[b][c][m0+j]
        const int m0 = blockIdx.x * 32;
        #pragma unroll
        for (int i2 = 0; i2 < 16; i2++) {
            int e = tid + i2 * 256;
            int c = e >> 5, j = e & 31;
            const __nv_bfloat16* r = T + c * TTS;
            float v = fmaxf(fmaxf(__bfloat162float(r[2 * j]),
                                  __bfloat162float(r[2 * j + 1])),
                            fmaxf(__bfloat162float(r[64 + 2 * j]),
                                  __bfloat162float(r[64 + 2 * j + 1])));
            g_VH[((size_t)b * CI + c) * MM + m0 + j] = __float2bfloat16(v);
        }
    }
}

// ---------------------------------------------------------------------------
// Kernel B: W_w fp32 [o][c] -> bf16 g_WH [o][c]
// ---------------------------------------------------------------------------
__global__ __launch_bounds__(256) void wprep_kernel(const float* __restrict__ W_w)
{
    const int idx = blockIdx.x * 256 + threadIdx.x;
    g_WH[idx] = __float2bfloat16(W_w[idx]);
}

// ---------------------------------------------------------------------------
// Kernel C (R10 structure, verified fastest): bf16 flash attention +
// fused final conv/BN/residual. Chunk 128 keys, Q frags in registers,
// W prefetched into smem (overlaps the whole mainloop). Softmax via raw
// ex2 (Q pre-scaled by log2e), fixed-max with clamp.
// ---------------------------------------------------------------------------
#define ROWB 272                   // 256B row + 16B pad
#define TBYTES (128 * ROWB)        // 34816 per buffer
#define OFF_K0 0
#define OFF_K1 TBYTES
#define OFF_V0 (2 * TBYTES)
#define OFF_V1 (3 * TBYTES)
#define OFF_WS (4 * TBYTES)                      // W tile: 256 rows x ROWB
#define ATTN_SMEM_BYTES (4 * TBYTES + 256 * ROWB)   // 208896

__global__ __launch_bounds__(256) void attn_kernel(
    const float* __restrict__ x,
    const float* __restrict__ W_b,
    const float* __restrict__ bn_gamma, const float* __restrict__ bn_beta,
    const float* __restrict__ bn_mean,  const float* __restrict__ bn_var,
    float* __restrict__ out)
{
    extern __shared__ char smc[];

    const int b  = blockIdx.y;
    const int q0 = blockIdx.x * 128;
    const int tid  = threadIdx.x;
    const int warp = tid >> 5, lane = tid & 31;
    const int g = lane >> 2, tig = lane & 3;
    const int qbase = warp * 16;

    // ---- prefetch W tile (consumed only in the epilogue) ----
    #pragma unroll
    for (int i = 0; i < 16; i++) {
        int gi = tid + i * 256;
        int o = gi >> 4, c16 = gi & 15;
        cp_async16(smc + OFF_WS + o * ROWB + c16 * 16,
                   (const char*)&g_WH[o * CI] + c16 * 16);
    }
    CP_COMMIT();

    // ---- stage Q into V0 region; overlap with K0 ----
    #pragma unroll
    for (int i = 0; i < 8; i++) {
        int gi = tid + i * 256;
        int n = gi >> 4, c16 = gi & 15;
        cp_async16(smc + OFF_V0 + n * ROWB + c16 * 16,
                   (const char*)&g_QH[((size_t)b * NN + q0 + n) * CI] + c16 * 16);
    }
    CP_COMMIT();
    #pragma unroll
    for (int i = 0; i < 8; i++) {          // K chunk 0
        int gi = tid + i * 256;
        int key = gi >> 4, c16 = gi & 15;
        cp_async16(smc + OFF_K0 + key * ROWB + c16 * 16,
                   (const char*)&g_KH[((size_t)b * MM + key) * CI] + c16 * 16);
    }
    CP_COMMIT();
    CP_WAIT1();                 // W + Q arrived (K0 may still be in flight)
    __syncthreads();

    uint32_t aQ[8][4];
    #pragma unroll
    for (int s = 0; s < 8; s++) {
        const char* base = smc + OFF_V0 + s * 32 + tig * 4;
        aQ[s][0] = *(const uint32_t*)(base + (qbase + g)     * ROWB);
        aQ[s][1] = *(const uint32_t*)(base + (qbase + g + 8) * ROWB);
        aQ[s][2] = *(const uint32_t*)(base + (qbase + g)     * ROWB + 16);
        aQ[s][3] = *(const uint32_t*)(base + (qbase + g + 8) * ROWB + 16);
    }
    __syncthreads();

    // V chunk 0
    #pragma unroll
    for (int i = 0; i < 8; i++) {
        int gi = tid + i * 256;
        int ch = gi >> 4, k16 = gi & 15;
        cp_async16(smc + OFF_V0 + ch * ROWB + k16 * 16,
                   (const char*)&g_VH[((size_t)b * CI + ch) * MM] + k16 * 16);
    }
    CP_COMMIT();

    float l_lo = 0.0f, l_hi = 0.0f;
    float yacc[16][4] = {};

    for (int mt = 0; mt < MM / 128; mt++) {
        CP_WAIT0();
        __syncthreads();

        if (mt + 1 < MM / 128) {
            const int m0n = (mt + 1) * 128;
            const int kb = ((mt + 1) & 1) ? OFF_K1 : OFF_K0;
            const int vb = ((mt + 1) & 1) ? OFF_V1 : OFF_V0;
            #pragma unroll
            for (int i = 0; i < 8; i++) {
                int gi = tid + i * 256;
                int key = gi >> 4, c16 = gi & 15;
                cp_async16(smc + kb + key * ROWB + c16 * 16,
                           (const char*)&g_KH[((size_t)b * MM + m0n + key) * CI] + c16 * 16);
            }
            #pragma unroll
            for (int i = 0; i < 8; i++) {
                int gi = tid + i * 256;
                int ch = gi >> 4, k16 = gi & 15;
                cp_async16(smc + vb + ch * ROWB + k16 * 16,
                           (const char*)&g_VH[((size_t)b * CI + ch) * MM + m0n] + k16 * 16);
            }
            CP_COMMIT();
        }

        const char* Kb = smc + ((mt & 1) ? OFF_K1 : OFF_K0);
        const char* Vb = smc + ((mt & 1) ? OFF_V1 : OFF_V0);
        const char* kwb = Kb + g * ROWB + tig * 4;
        const char* vwb = Vb + g * ROWB + tig * 4;

        // ---- S = Q K^T  (128 keys) ----
        float sacc[16][4] = {};
        #pragma unroll
        for (int s = 0; s < 8; s++) {
            #pragma unroll
            for (int nt = 0; nt < 16; nt++) {
                uint32_t b0 = *(const uint32_t*)(kwb + nt * (8 * ROWB) + s * 32);
                uint32_t b1 = *(const uint32_t*)(kwb + nt * (8 * ROWB) + s * 32 + 16);
                mma_bf16(sacc[nt], aQ[s][0], aQ[s][1], aQ[s][2], aQ[s][3], b0, b1);
            }
        }

        // ---- fixed-max softmax: p = 2^(min(s', 115)), s' = s*log2e ----
        #pragma unroll
        for (int nt = 0; nt < 16; nt++) {
            sacc[nt][0] = ex2f(fminf(sacc[nt][0], 115.0f));
            sacc[nt][1] = ex2f(fminf(sacc[nt][1], 115.0f));
            sacc[nt][2] = ex2f(fminf(sacc[nt][2], 115.0f));
            sacc[nt][3] = ex2f(fminf(sacc[nt][3], 115.0f));
            l_lo += sacc[nt][0] + sacc[nt][1];
            l_hi += sacc[nt][2] + sacc[nt][3];
        }

        // ---- Y += P V^T ----
        #pragma unroll
        for (int s2 = 0; s2 < 8; s2++) {
            uint32_t a0 = pack_bf16(sacc[2*s2][0],   sacc[2*s2][1]);
            uint32_t a1 = pack_bf16(sacc[2*s2][2],   sacc[2*s2][3]);
            uint32_t a2 = pack_bf16(sacc[2*s2+1][0], sacc[2*s2+1][1]);
            uint32_t a3 = pack_bf16(sacc[2*s2+1][2], sacc[2*s2+1][3]);
            #pragma unroll
            for (int nt = 0; nt < 16; nt++) {
                uint32_t b0 = *(const uint32_t*)(vwb + nt * (8 * ROWB) + s2 * 32);
                uint32_t b1 = *(const uint32_t*)(vwb + nt * (8 * ROWB) + s2 * 32 + 16);
                mma_bf16(yacc[nt], a0, a1, a2, a3, b0, b1);
            }
        }
    }

    // ---- normalize y, write bf16 into Ys (aliases K0 buffer; idle now) ----
    l_lo += __shfl_xor_sync(0xffffffffu, l_lo, 1);
    l_lo += __shfl_xor_sync(0xffffffffu, l_lo, 2);
    l_hi += __shfl_xor_sync(0xffffffffu, l_hi, 1);
    l_hi += __shfl_xor_sync(0xffffffffu, l_hi, 2);
    const float inv_lo = 1.0f / l_lo;
    const float inv_hi = 1.0f / l_hi;

    char* Ysb = smc + OFF_K0;    // rows = n (local query), cols = c
    #pragma unroll
    for (int nt = 0; nt < 16; nt++) {
        const int c = nt * 8 + tig * 2;
        uint32_t plo = pack_bf16(yacc[nt][0] * inv_lo, yacc[nt][1] * inv_lo);
        uint32_t phi = pack_bf16(yacc[nt][2] * inv_hi, yacc[nt][3] * inv_hi);
        *(uint32_t*)(Ysb + (qbase + g)     * ROWB + c * 2) = plo;
        *(uint32_t*)(Ysb + (qbase + g + 8) * ROWB + c * 2) = phi;
    }
    __syncthreads();

    // ---- fused final conv: out[o][n] = BN(W@y + W_b) + x ----
    // warp w handles o-tile [w*32, w*32+32) x all 128 n
    const int obase2 = warp * 32;
    const char* Wsb = smc + OFF_WS;
    const char* ywb = Ysb + g * ROWB + tig * 4;

    float facc[2][16][4] = {};
    #pragma unroll
    for (int s = 0; s < 8; s++) {
        uint32_t aw[2][4];
        #pragma unroll
        for (int mi = 0; mi < 2; mi++) {
            const char* base = Wsb + (obase2 + mi * 16 + g) * ROWB + s * 32 + tig * 4;
            aw[mi][0] = *(const uint32_t*)(base);
            aw[mi][1] = *(const uint32_t*)(base + 8 * ROWB);
            aw[mi][2] = *(const uint32_t*)(base + 16);
            aw[mi][3] = *(const uint32_t*)(base + 8 * ROWB + 16);
        }
        #pragma unroll
        for (int nt = 0; nt < 16; nt++) {
            uint32_t b0 = *(const uint32_t*)(ywb + nt * (8 * ROWB) + s * 32);
            uint32_t b1 = *(const uint32_t*)(ywb + nt * (8 * ROWB) + s * 32 + 16);
            mma_bf16(facc[0][nt], aw[0][0], aw[0][1], aw[0][2], aw[0][3], b0, b1);
            mma_bf16(facc[1][nt], aw[1][0], aw[1][1], aw[1][2], aw[1][3], b0, b1);
        }
    }

    // ---- BN + bias + residual epilogue ----
    #pragma unroll
    for (int mi = 0; mi < 2; mi++) {
        #pragma unroll
        for (int half = 0; half < 2; half++) {
            const int o = obase2 + mi * 16 + g + half * 8;
            const float scale = bn_gamma[o] * rsqrtf(bn_var[o] + 1e-5f);
            const float shift = bn_beta[o] - bn_mean[o] * scale + W_b[o] * scale;
            const size_t base = ((size_t)b * CC + o) * NN + q0;
            #pragma unroll
            for (int nt = 0; nt < 16; nt++) {
                const int n = nt * 8 + tig * 2;
                float2 xr = *(const float2*)&x[base + n];
                float2 v;
                v.x = facc[mi][nt][half * 2 + 0] * scale + shift + xr.x;
                v.y = facc[mi][nt][half * 2 + 1] * scale + shift + xr.y;
                *(float2*)&out[base + n] = v;
            }
        }
    }
}

// ---------------------------------------------------------------------------
// Launch
// ---------------------------------------------------------------------------
extern "C" void kernel_launch(void* const* d_in, const int* in_sizes, int n_in,
                              void* d_out, int out_size)
{
    (void)in_sizes; (void)n_in; (void)out_size;

    const float* x        = (const float*)d_in[0];
    const float* theta_w  = (const float*)d_in[1];
    const float* theta_b  = (const float*)d_in[2];
    const float* phi_w    = (const float*)d_in[3];
    const float* phi_b    = (const float*)d_in[4];
    const float* gw       = (const float*)d_in[5];
    const float* gb       = (const float*)d_in[6];
    const float* W_w      = (const float*)d_in[7];
    const float* W_b      = (const float*)d_in[8];
    const float* bn_gamma = (const float*)d_in[9];
    const float* bn_beta  = (const float*)d_in[10];
    const float* bn_mean  = (const float*)d_in[11];
    const float* bn_var   = (const float*)d_in[12];
    float* out = (float*)d_out;

    cudaFuncSetAttribute(proj_kernel,
                         cudaFuncAttributeMaxDynamicSharedMemorySize, PROJ_SMEM_BYTES);
    cudaFuncSetAttribute(attn_kernel,
                         cudaFuncAttributeMaxDynamicSharedMemorySize, ATTN_SMEM_BYTES);

    // A: projections with fused pool/transpose epilogues
    {
        dim3 grid(32, 3, BB);
        proj_kernel<<<grid, 256, PROJ_SMEM_BYTES>>>(x, theta_w, theta_b,
                                                    phi_w, phi_b, gw, gb);
    }
    // B: W -> bf16
    wprep_kernel<<<(CC * CI) / 256, 256>>>(W_w);
    // C: flash attention + fused final conv/BN/residual
    {
        dim3 grid(NN / 128, BB);
        attn_kernel<<<grid, 256, ATTN_SMEM_BYTES>>>(x, W_b, bn_gamma, bn_beta,
                                                    bn_mean, bn_var, out);
    }
}